// round 14
// baseline (speedup 1.0000x reference)
#include <cuda_runtime.h>
#include <cuda_bf16.h>

#define FDIM 224
#define NORD 15
#define NMAX 25008
#define PMAX 400128
#define TE   128

__device__ float g_q[NMAX * FDIM];
__device__ float g_k[NMAX * FDIM];
__device__ float g_v[NMAX * FDIM];
__device__ float g_alpha[(size_t)PMAX * 8];
__device__ unsigned g_Bf[2 * 14 * 7 * 32 * 8];   // B2 fragments (hi uint4, lo uint4)

// smem byte offsets
#define OFF_CUT   0
#define OFF_B2C   512
#define OFF_II    1408
#define OFF_JJ    1920
#define OFF_L0    2432
// phase 1 (GEMM1 operands), dead after GEMM1:
#define OFF_B1H   4096
#define OFF_B1L   29184
#define OFF_A1H   54272
#define OFF_A1L   68608
// phase 2 (A2 hi/lo, ldmatrix layout, 464 B row stride), overlays phase 1:
#define OFF_A2H   4096
#define OFF_A2L   63488
// phase 3 (w f32, 228-float row stride), overlays phase 2:
#define OFF_WS    4096
// B2 panel double buffer (above A2 region, never overlaid):
#define OFF_PAN   122880
#define PAN_SZ    28672
#define PAN_LO    14336
#define SM_TOTAL  180224

__device__ __forceinline__ unsigned smem_u32(const void* p) {
    unsigned a;
    asm("{ .reg .u64 t; cvta.to.shared.u64 t, %1; cvt.u32.u64 %0, t; }" : "=r"(a) : "l"(p));
    return a;
}
__device__ __forceinline__ float silu_f(float x) {
    return __fdividef(x, 1.0f + __expf(-x));
}
__device__ __forceinline__ void ldm4(unsigned* r, unsigned addr) {
    asm volatile("ldmatrix.sync.aligned.m8n8.x4.shared.b16 {%0,%1,%2,%3}, [%4];"
                 : "=r"(r[0]), "=r"(r[1]), "=r"(r[2]), "=r"(r[3]) : "r"(addr) : "memory");
}
__device__ __forceinline__ void mmabf(float* c, const unsigned* a, const unsigned* b) {
    asm volatile("mma.sync.aligned.m16n8k16.row.col.f32.bf16.bf16.f32 "
                 "{%0,%1,%2,%3}, {%4,%5,%6,%7}, {%8,%9}, {%0,%1,%2,%3};"
                 : "+f"(c[0]), "+f"(c[1]), "+f"(c[2]), "+f"(c[3])
                 : "r"(a[0]), "r"(a[1]), "r"(a[2]), "r"(a[3]), "r"(b[0]), "r"(b[1]));
}
__device__ __forceinline__ unsigned packbf(float a, float b) {
    __nv_bfloat162 t = __floats2bfloat162_rn(a, b);
    return *(unsigned*)&t;
}
__device__ __forceinline__ void split2(float a, float b, unsigned& hi, unsigned& lo) {
    __nv_bfloat162 h = __floats2bfloat162_rn(a, b);
    hi = *(unsigned*)&h;
    lo = packbf(a - __bfloat162float(h.x), b - __bfloat162float(h.y));
}
__device__ __forceinline__ void cpa16(unsigned dst, const void* src) {
    asm volatile("cp.async.cg.shared.global [%0], [%1], 16;" :: "r"(dst), "l"(src) : "memory");
}

// Copy one 2-ks k-block of B fragments (both p halves, hi+lo) into panel buffer.
#define COPY_KB(kb, buf) do {                                                 \
    const unsigned _d = sb + OFF_PAN + (buf) * PAN_SZ;                        \
    for (int _i = t; _i < 896; _i += 512) {                                   \
        int _Le = _i & 31, _r = _i >> 5;                                      \
        int _j2 = _r % 7, _pq = _r / 7;                                       \
        int _pp = _pq & 1, _ksl = _pq >> 1;                                   \
        int _gid = ((_pp * 14 + (kb) * 2 + _ksl) * 7 + _j2) * 32 + _Le;       \
        cpa16(_d + _i * 16, (const uint4*)g_Bf + _gid * 2);                   \
        cpa16(_d + PAN_LO + _i * 16, (const uint4*)g_Bf + _gid * 2 + 1);      \
    }                                                                         \
    asm volatile("cp.async.commit_group;" ::: "memory");                      \
} while (0)

__global__ void zero_kernel(float* out, int n) {
    int i = blockIdx.x * blockDim.x + threadIdx.x;
    if (i < n) out[i] = 0.0f;
}

// Pre-pack W2cat into per-lane MMA B fragments.
// entry id = ((p*14+ks)*7+j2)*32 + L  ->  8 unsigneds: bh[4], bl[4]
__global__ void prep_bf_kernel(const float* __restrict__ W2r, const float* __restrict__ W2s) {
    int id = blockIdx.x * blockDim.x + threadIdx.x;
    if (id >= 6272) return;
    int L = id & 31, rest = id >> 5;
    int j2 = rest % 7, pk = rest / 7;
    int ks = pk % 14, p = pk / 14;
    int n0 = p * 112 + j2 * 16 + (L >> 2);
    int c0 = ks * 16 + (L & 3) * 2;
    unsigned u[8];
#pragma unroll
    for (int i = 0; i < 4; i++) {
        int n = n0 + (i >> 1) * 8;
        int c = c0 + (i & 1) * 8;
        float V0 = (c < 112) ? W2r[c * 224 + n] : W2s[(c - 112) * 224 + n];
        float V1 = (c + 1 < 112) ? W2r[(c + 1) * 224 + n] : W2s[(c + 1 - 112) * 224 + n];
        split2(V0, V1, u[i], u[4 + i]);
    }
    uint4* dst = (uint4*)g_Bf + id * 2;
    dst[0] = make_uint4(u[0], u[1], u[2], u[3]);
    dst[1] = make_uint4(u[4], u[5], u[6], u[7]);
}

__global__ __launch_bounds__(224) void node_kernel(
    const float* __restrict__ x, const float* __restrict__ Wq,
    const float* __restrict__ Wk, const float* __restrict__ Wv, int N)
{
    __shared__ float xs[FDIM];
    const int c = threadIdx.x;
    const int h = c >> 5, i = c & 31;
    const int h2 = c / 56, i2 = c - h2 * 56;
    float4 wq[8], wk[8], wv[14];
    const float4* q4 = (const float4*)(Wq + (h * 32 + i) * 32);
    const float4* k4 = (const float4*)(Wk + (h * 32 + i) * 32);
    const float4* v4 = (const float4*)(Wv + (h2 * 56 + i2) * 56);
#pragma unroll
    for (int m = 0; m < 8; m++) { wq[m] = q4[m]; wk[m] = k4[m]; }
#pragma unroll
    for (int m = 0; m < 14; m++) wv[m] = v4[m];
    for (int n = blockIdx.x; n < N; n += gridDim.x) {
        __syncthreads();
        xs[c] = x[(size_t)n * FDIM + c];
        __syncthreads();
        float aq = 0.f, ak = 0.f, av = 0.f;
        const float4* xb = (const float4*)(xs + h * 32);
#pragma unroll
        for (int m = 0; m < 8; m++) {
            float4 xv = xb[m];
            aq += wq[m].x * xv.x + wq[m].y * xv.y + wq[m].z * xv.z + wq[m].w * xv.w;
            ak += wk[m].x * xv.x + wk[m].y * xv.y + wk[m].z * xv.z + wk[m].w * xv.w;
        }
        const float4* xb2 = (const float4*)(xs + h2 * 56);
#pragma unroll
        for (int m = 0; m < 14; m++) {
            float4 xv = xb2[m];
            av += wv[m].x * xv.x + wv[m].y * xv.y + wv[m].z * xv.z + wv[m].w * xv.w;
        }
        g_q[(size_t)n * FDIM + c] = silu_f(aq);
        g_k[(size_t)n * FDIM + c] = silu_f(ak);
        g_v[(size_t)n * FDIM + c] = av;
    }
}

// 512 threads, 16 warps: warp w -> (g = w>>1: rows 16g..16g+15, p = w&1: cols 112p..)
__global__ __launch_bounds__(512, 1) void fused_edge_kernel(
    const float* __restrict__ rbf, const float* __restrict__ cut,
    const int* __restrict__ idx_i, const int* __restrict__ idx_j,
    const float* __restrict__ ev,
    const float* __restrict__ W1r, const float* __restrict__ b1r,
    const float* __restrict__ W1s, const float* __restrict__ b1s,
    const float* __restrict__ b2r, const float* __restrict__ b2s, int P)
{
    extern __shared__ char smc[];
    const unsigned sb = smem_u32(smc);
    const int t = threadIdx.x, w = t >> 5, L = t & 31;
    const int g = w >> 1, p = w & 1;
    const int rw = g * 16;
    const int e0 = blockIdx.x * TE;

    float* cut_s = (float*)(smc + OFF_CUT);
    float* b2c_s = (float*)(smc + OFF_B2C);
    int*   ii_s  = (int*)(smc + OFF_II);
    int*   jj_s  = (int*)(smc + OFF_JJ);
    float* l0_s  = (float*)(smc + OFF_L0);

    // ---- stage misc + B1 (hi/lo) ----
    if (t < 224) b2c_s[t] = b2r[t] + b2s[t];
    if (t < TE) {
        int eg = min(e0 + t, P - 1);
        int a = idx_i[eg], b = idx_j[eg];
        ii_s[t] = a; jj_s[t] = b;
        cut_s[t] = (e0 + t < P) ? cut[e0 + t] : 0.f;
        float s0 = 0.f, s1 = 0.f, s2 = 0.f;
        const float* ea = ev + a * NORD;
        const float* eb = ev + b * NORD;
#pragma unroll
        for (int o = 0; o < NORD; o++) {
            float d = eb[o] - ea[o];
            float dd = d * d;
            if (o < 3) s0 += dd; else if (o < 8) s1 += dd; else s2 += dd;
        }
        l0_s[t] = s0; l0_s[128 + t] = s1; l0_s[256 + t] = s2;
    }
    for (int i = t; i < 224 * 48; i += 512) {
        int n = i / 48, k = i - n * 48;
        float v = 0.f;
        if (n < 112) {
            if (k < 32) v = W1r[k * 112 + n];
            else if (k == 35) v = b1r[n];
        } else {
            int n2 = n - 112;
            if (k >= 32 && k < 35) v = W1s[(k - 32) * 112 + n2];
            else if (k == 35) v = b1s[n2];
        }
        __nv_bfloat16 hv = __float2bfloat16(v);
        ((__nv_bfloat16*)(smc + OFF_B1H))[n * 56 + k] = hv;
        ((__nv_bfloat16*)(smc + OFF_B1L))[n * 56 + k] =
            __float2bfloat16(v - __bfloat162float(hv));
    }
    __syncthreads();
    for (int i = t; i < TE * 48; i += 512) {
        int e = i / 48, k = i - e * 48;
        float v = 0.f;
        if (k < 32)      v = ((e0 + e < P) ? rbf[(size_t)(e0 + e) * 32 + k] : 0.f) * cut_s[e];
        else if (k < 35) v = l0_s[(k - 32) * 128 + e];
        else if (k == 35) v = 1.f;
        __nv_bfloat16 hv = __float2bfloat16(v);
        ((__nv_bfloat16*)(smc + OFF_A1H))[e * 56 + k] = hv;
        ((__nv_bfloat16*)(smc + OFF_A1L))[e * 56 + k] =
            __float2bfloat16(v - __bfloat162float(hv));
    }
    __syncthreads();

    // issue B2 panel 0 copy now — hides under GEMM1 compute
    COPY_KB(0, 0);

    // ---- GEMM1: c1[14][4] = A1 @ B1^T  (N-half p) ----
    unsigned ah1[3][4], al1[3][4];
#pragma unroll
    for (int ks = 0; ks < 3; ks++) {
        unsigned row = rw + (L & 15), col = ks * 16 + (L >> 4) * 8;
        ldm4(ah1[ks], sb + OFF_A1H + (row * 56 + col) * 2);
        ldm4(al1[ks], sb + OFF_A1L + (row * 56 + col) * 2);
    }
    float c1[14][4];
#pragma unroll
    for (int j = 0; j < 14; j++)
#pragma unroll
        for (int q = 0; q < 4; q++) c1[j][q] = 0.f;
#pragma unroll
    for (int j2 = 0; j2 < 7; j2++) {
        unsigned n0 = p * 112 + j2 * 16 + (L >> 4) * 8 + (L & 7);
#pragma unroll
        for (int ks = 0; ks < 3; ks++) {
            unsigned off = n0 * 112 + ks * 32 + ((L >> 3) & 1) * 16;
            unsigned bh[4], bl[4];
            ldm4(bh, sb + OFF_B1H + off);
            ldm4(bl, sb + OFF_B1L + off);
            mmabf(c1[2 * j2], ah1[ks], bh);
            mmabf(c1[2 * j2 + 1], ah1[ks], bh + 2);
            mmabf(c1[2 * j2], al1[ks], bh);
            mmabf(c1[2 * j2 + 1], al1[ks], bh + 2);
            mmabf(c1[2 * j2], ah1[ks], bl);
            mmabf(c1[2 * j2 + 1], ah1[ks], bl + 2);
        }
    }
    __syncthreads();   // all GEMM1 smem reads done; A2 overlay safe

    // ---- silu + split -> A2h/A2l smem (ldmatrix layout, 464 B stride) ----
    {
        const int rA = rw + (L >> 2);
        const int cb = 2 * (L & 3);
        char* a2h = smc + OFF_A2H;
        char* a2l = smc + OFF_A2L;
#pragma unroll
        for (int j = 0; j < 7; j++) {
            const int c0 = p * 112 + j * 16 + cb;
            float v0 = silu_f(c1[2 * j][0]), v1 = silu_f(c1[2 * j][1]);
            float v2 = silu_f(c1[2 * j][2]), v3 = silu_f(c1[2 * j][3]);
            float v4 = silu_f(c1[2 * j + 1][0]), v5 = silu_f(c1[2 * j + 1][1]);
            float v6 = silu_f(c1[2 * j + 1][2]), v7 = silu_f(c1[2 * j + 1][3]);
            unsigned hi, lo;
            split2(v0, v1, hi, lo);
            *(unsigned*)(a2h + rA * 464 + c0 * 2) = hi;
            *(unsigned*)(a2l + rA * 464 + c0 * 2) = lo;
            split2(v2, v3, hi, lo);
            *(unsigned*)(a2h + (rA + 8) * 464 + c0 * 2) = hi;
            *(unsigned*)(a2l + (rA + 8) * 464 + c0 * 2) = lo;
            split2(v4, v5, hi, lo);
            *(unsigned*)(a2h + rA * 464 + (c0 + 8) * 2) = hi;
            *(unsigned*)(a2l + rA * 464 + (c0 + 8) * 2) = lo;
            split2(v6, v7, hi, lo);
            *(unsigned*)(a2h + (rA + 8) * 464 + (c0 + 8) * 2) = hi;
            *(unsigned*)(a2l + (rA + 8) * 464 + (c0 + 8) * 2) = lo;
        }
    }
    asm volatile("cp.async.wait_group 0;" ::: "memory");
    __syncthreads();   // A2 + panel 0 visible

    // ---- GEMM2: 7 k-blocks, cp.async double-buffered smem B panels ----
    float c2[14][4];
#pragma unroll
    for (int j = 0; j < 14; j++)
#pragma unroll
        for (int q = 0; q < 4; q++) c2[j][q] = 0.f;
    const unsigned a2h_row = sb + OFF_A2H + (rw + (L & 15)) * 464 + ((L >> 4) * 8) * 2;
    const unsigned a2l_row = sb + OFF_A2L + (rw + (L & 15)) * 464 + ((L >> 4) * 8) * 2;

#pragma unroll 1
    for (int kb = 0; kb < 7; kb++) {
        if (kb < 6) COPY_KB(kb + 1, (kb + 1) & 1);
        const char* pan = smc + OFF_PAN + (kb & 1) * PAN_SZ;
#pragma unroll
        for (int ksl = 0; ksl < 2; ksl++) {
            const int ks = kb * 2 + ksl;
            unsigned Ah[4], Al[4];
            ldm4(Ah, a2h_row + ks * 32);
            ldm4(Al, a2l_row + ks * 32);
#pragma unroll
            for (int j2 = 0; j2 < 7; j2++) {
                const int ent = (((ksl * 2 + p) * 7 + j2) * 32 + L) * 16;
                uint4 bh4 = *(const uint4*)(pan + ent);
                uint4 bl4 = *(const uint4*)(pan + PAN_LO + ent);
                const unsigned* bh = (const unsigned*)&bh4;
                const unsigned* bl = (const unsigned*)&bl4;
                mmabf(c2[2 * j2], Ah, bh);
                mmabf(c2[2 * j2 + 1], Ah, bh + 2);
                mmabf(c2[2 * j2], Al, bh);
                mmabf(c2[2 * j2 + 1], Al, bh + 2);
                mmabf(c2[2 * j2], Ah, bl);
                mmabf(c2[2 * j2 + 1], Ah, bl + 2);
            }
        }
        asm volatile("cp.async.wait_group 0;" ::: "memory");
        __syncthreads();
    }

    // ---- write w (raw, no bias) to smem f32 ----
    {
        float* ws = (float*)(smc + OFF_WS);
        const int rA = rw + (L >> 2);
        const int cb = 2 * (L & 3);
#pragma unroll
        for (int j2 = 0; j2 < 7; j2++) {
            const int c0 = p * 112 + j2 * 16 + cb;
            ws[rA * 228 + c0]           = c2[2 * j2][0];
            ws[rA * 228 + c0 + 1]       = c2[2 * j2][1];
            ws[(rA + 8) * 228 + c0]     = c2[2 * j2][2];
            ws[(rA + 8) * 228 + c0 + 1] = c2[2 * j2][3];
            ws[rA * 228 + c0 + 8]           = c2[2 * j2 + 1][0];
            ws[rA * 228 + c0 + 9]           = c2[2 * j2 + 1][1];
            ws[(rA + 8) * 228 + c0 + 8]     = c2[2 * j2 + 1][2];
            ws[(rA + 8) * 228 + c0 + 9]     = c2[2 * j2 + 1][3];
        }
    }
    __syncthreads();

    // ---- epilogue: alpha[e][h] = cut * sum_c q_i[c] k_j[c] (w[c]+b2[c]) ----
    {
        const float* ws = (const float*)(smc + OFF_WS);
        const int e = t & 127;
        const int hb = t >> 7;           // 0..3
        const int ni = ii_s[e], nj = jj_s[e];
        const float ce = cut_s[e];
        const float* qp = g_q + (size_t)ni * FDIM;
        const float* kp = g_k + (size_t)nj * FDIM;
#pragma unroll
        for (int it = 0; it < 2; it++) {
            const int h = hb + 4 * it;
            if (h < 7) {
                float s = 0.f;
#pragma unroll
                for (int m = 0; m < 8; m++) {
                    const int c = h * 32 + 4 * m;
                    float4 q4 = *(const float4*)(qp + c);
                    float4 k4 = *(const float4*)(kp + c);
                    s += q4.x * k4.x * (ws[e * 228 + c]     + b2c_s[c]);
                    s += q4.y * k4.y * (ws[e * 228 + c + 1] + b2c_s[c + 1]);
                    s += q4.z * k4.z * (ws[e * 228 + c + 2] + b2c_s[c + 2]);
                    s += q4.w * k4.w * (ws[e * 228 + c + 3] + b2c_s[c + 3]);
                }
                if (e0 + e < P) g_alpha[(size_t)(e0 + e) * 8 + h] = s * ce;
            }
        }
    }
}

__global__ __launch_bounds__(256) void scatter_kernel(
    const float* __restrict__ ylm, const int* __restrict__ idx_i,
    const int* __restrict__ idx_j, float* __restrict__ outx,
    float* __restrict__ outev, int P)
{
    __shared__ float alp_s[7 * TE];
    __shared__ float ylm_s[TE * NORD];
    __shared__ int ii_s[TE], jj_s[TE];
    const int t = threadIdx.x;
    const int e0 = blockIdx.x * TE;
    const int nE = min(TE, P - e0);

    if (t < TE) {
        int eg = min(e0 + t, P - 1);
        ii_s[t] = idx_i[eg];
        jj_s[t] = idx_j[eg];
    }
    for (int i = t; i < 7 * TE; i += 256) {
        int h = i >> 7, e = i & 127;
        alp_s[i] = (e0 + e < P) ? g_alpha[(size_t)(e0 + e) * 8 + h] : 0.f;
    }
    for (int i = t; i < TE * NORD; i += 256)
        ylm_s[i] = (e0 + i / NORD < P) ? ylm[(size_t)e0 * NORD + i] : 0.f;
    __syncthreads();

    if (t < FDIM) {
        int hc = t / 56;
        const float* arow = alp_s + hc * TE;
        int icur = ii_s[0];
        float a2 = 0.f;
        for (int e = 0; e < nE; e++) {
            int ie = ii_s[e];
            if (ie != icur) {
                atomicAdd(outx + (size_t)icur * FDIM + t, a2);
                a2 = 0.f; icur = ie;
            }
            a2 += arow[e] * g_v[(size_t)jj_s[e] * FDIM + t];
        }
        atomicAdd(outx + (size_t)icur * FDIM + t, a2);
    } else if (t < FDIM + NORD) {
        int o = t - FDIM;
        int hd = (o < 3) ? 4 : (o < 8) ? 5 : 6;
        const float* arow = alp_s + hd * TE;
        int icur = ii_s[0];
        float a2 = 0.f;
        for (int e = 0; e < nE; e++) {
            int ie = ii_s[e];
            if (ie != icur) {
                atomicAdd(outev + (size_t)icur * NORD + o, a2);
                a2 = 0.f; icur = ie;
            }
            a2 += arow[e] * ylm_s[e * NORD + o];
        }
        atomicAdd(outev + (size_t)icur * NORD + o, a2);
    }
}

extern "C" void kernel_launch(void* const* d_in, const int* in_sizes, int n_in,
                              void* d_out, int out_size)
{
    const float* x    = (const float*)d_in[0];
    const float* ev   = (const float*)d_in[1];
    const float* rbf  = (const float*)d_in[2];
    const float* ylm  = (const float*)d_in[3];
    const float* cutp = (const float*)d_in[4];
    const int*   idxi = (const int*)d_in[5];
    const int*   idxj = (const int*)d_in[6];
    const float* W1r  = (const float*)d_in[7];
    const float* b1r  = (const float*)d_in[8];
    const float* W2r  = (const float*)d_in[9];
    const float* b2r  = (const float*)d_in[10];
    const float* W1s  = (const float*)d_in[11];
    const float* b1s  = (const float*)d_in[12];
    const float* W2s  = (const float*)d_in[13];
    const float* b2s  = (const float*)d_in[14];
    const float* Wq   = (const float*)d_in[15];
    const float* Wk   = (const float*)d_in[16];
    const float* Wv   = (const float*)d_in[17];

    int N = in_sizes[0] / FDIM;
    int P = in_sizes[4];
    float* out   = (float*)d_out;
    float* outx  = out;
    float* outev = out + (size_t)N * FDIM;

    zero_kernel<<<(out_size + 255) / 256, 256>>>(out, out_size);
    prep_bf_kernel<<<(6272 + 255) / 256, 256>>>(W2r, W2s);
    node_kernel<<<1024, 224>>>(x, Wq, Wk, Wv, N);

    cudaFuncSetAttribute(fused_edge_kernel,
                         cudaFuncAttributeMaxDynamicSharedMemorySize, SM_TOTAL);
    int nb = (P + TE - 1) / TE;
    fused_edge_kernel<<<nb, 512, SM_TOTAL>>>(rbf, cutp, idxi, idxj, ev,
                                             W1r, b1r, W1s, b1s, b2r, b2s, P);
    scatter_kernel<<<nb, 256>>>(ylm, idxi, idxj, outx, outev, P);
}

// round 15
// speedup vs baseline: 1.0288x; 1.0288x over previous
#include <cuda_runtime.h>
#include <cuda_bf16.h>

#define FDIM 224
#define NORD 15
#define NMAX 25008
#define PMAX 400128
#define TE   128

__device__ float g_q[NMAX * FDIM];
__device__ float g_k[NMAX * FDIM];
__device__ float g_v[NMAX * FDIM];
__device__ float g_alpha[(size_t)PMAX * 8];
__device__ unsigned g_Bf[2 * 14 * 7 * 32 * 8];   // B2 fragments (hi uint4, lo uint4)

// smem byte offsets
#define OFF_CUT   0
#define OFF_B2C   512
#define OFF_II    1408
#define OFF_JJ    1920
#define OFF_L0    2432
// phase 1 (GEMM1 operands), dead after GEMM1:
#define OFF_B1H   4096
#define OFF_B1L   29184
#define OFF_A1H   54272
#define OFF_A1L   68608
// phase 2 (A2 hi/lo, ldmatrix layout, 464 B row stride), overlays phase 1:
#define OFF_A2H   4096
#define OFF_A2L   63488
// phase 3 (w f32, 228-float row stride), overlays phase 2:
#define OFF_WS    4096
#define SM_TOTAL  122880

__device__ __forceinline__ unsigned smem_u32(const void* p) {
    unsigned a;
    asm("{ .reg .u64 t; cvta.to.shared.u64 t, %1; cvt.u32.u64 %0, t; }" : "=r"(a) : "l"(p));
    return a;
}
__device__ __forceinline__ float silu_f(float x) {
    return __fdividef(x, 1.0f + __expf(-x));
}
__device__ __forceinline__ void ldm4(unsigned* r, unsigned addr) {
    asm volatile("ldmatrix.sync.aligned.m8n8.x4.shared.b16 {%0,%1,%2,%3}, [%4];"
                 : "=r"(r[0]), "=r"(r[1]), "=r"(r[2]), "=r"(r[3]) : "r"(addr) : "memory");
}
__device__ __forceinline__ void mmabf(float* c, const unsigned* a, const unsigned* b) {
    asm volatile("mma.sync.aligned.m16n8k16.row.col.f32.bf16.bf16.f32 "
                 "{%0,%1,%2,%3}, {%4,%5,%6,%7}, {%8,%9}, {%0,%1,%2,%3};"
                 : "+f"(c[0]), "+f"(c[1]), "+f"(c[2]), "+f"(c[3])
                 : "r"(a[0]), "r"(a[1]), "r"(a[2]), "r"(a[3]), "r"(b[0]), "r"(b[1]));
}
__device__ __forceinline__ unsigned packbf(float a, float b) {
    __nv_bfloat162 t = __floats2bfloat162_rn(a, b);
    return *(unsigned*)&t;
}
__device__ __forceinline__ void split2(float a, float b, unsigned& hi, unsigned& lo) {
    __nv_bfloat162 h = __floats2bfloat162_rn(a, b);
    hi = *(unsigned*)&h;
    lo = packbf(a - __bfloat162float(h.x), b - __bfloat162float(h.y));
}

__global__ void zero_kernel(float* out, int n) {
    int i = blockIdx.x * blockDim.x + threadIdx.x;
    int n4 = n >> 2;
    if (i < n4) ((float4*)out)[i] = make_float4(0.f, 0.f, 0.f, 0.f);
    if (i < (n & 3)) out[n4 * 4 + i] = 0.f;
}

// Pre-pack W2cat into per-lane MMA B fragments.
// entry id = ((p*14+ks)*7+j2)*32 + L  ->  8 unsigneds: bh[4], bl[4]
__global__ void prep_bf_kernel(const float* __restrict__ W2r, const float* __restrict__ W2s) {
    int id = blockIdx.x * blockDim.x + threadIdx.x;
    if (id >= 6272) return;
    int L = id & 31, rest = id >> 5;
    int j2 = rest % 7, pk = rest / 7;
    int ks = pk % 14, p = pk / 14;
    int n0 = p * 112 + j2 * 16 + (L >> 2);
    int c0 = ks * 16 + (L & 3) * 2;
    unsigned u[8];
#pragma unroll
    for (int i = 0; i < 4; i++) {
        int n = n0 + (i >> 1) * 8;
        int c = c0 + (i & 1) * 8;
        float V0 = (c < 112) ? W2r[c * 224 + n] : W2s[(c - 112) * 224 + n];
        float V1 = (c + 1 < 112) ? W2r[(c + 1) * 224 + n] : W2s[(c + 1 - 112) * 224 + n];
        split2(V0, V1, u[i], u[4 + i]);
    }
    uint4* dst = (uint4*)g_Bf + id * 2;
    dst[0] = make_uint4(u[0], u[1], u[2], u[3]);
    dst[1] = make_uint4(u[4], u[5], u[6], u[7]);
}

__global__ __launch_bounds__(224) void node_kernel(
    const float* __restrict__ x, const float* __restrict__ Wq,
    const float* __restrict__ Wk, const float* __restrict__ Wv, int N)
{
    __shared__ float xs[FDIM];
    const int c = threadIdx.x;
    const int h = c >> 5, i = c & 31;
    const int h2 = c / 56, i2 = c - h2 * 56;
    float4 wq[8], wk[8], wv[14];
    const float4* q4 = (const float4*)(Wq + (h * 32 + i) * 32);
    const float4* k4 = (const float4*)(Wk + (h * 32 + i) * 32);
    const float4* v4 = (const float4*)(Wv + (h2 * 56 + i2) * 56);
#pragma unroll
    for (int m = 0; m < 8; m++) { wq[m] = q4[m]; wk[m] = k4[m]; }
#pragma unroll
    for (int m = 0; m < 14; m++) wv[m] = v4[m];
    for (int n = blockIdx.x; n < N; n += gridDim.x) {
        __syncthreads();
        xs[c] = x[(size_t)n * FDIM + c];
        __syncthreads();
        float aq = 0.f, ak = 0.f, av = 0.f;
        const float4* xb = (const float4*)(xs + h * 32);
#pragma unroll
        for (int m = 0; m < 8; m++) {
            float4 xv = xb[m];
            aq += wq[m].x * xv.x + wq[m].y * xv.y + wq[m].z * xv.z + wq[m].w * xv.w;
            ak += wk[m].x * xv.x + wk[m].y * xv.y + wk[m].z * xv.z + wk[m].w * xv.w;
        }
        const float4* xb2 = (const float4*)(xs + h2 * 56);
#pragma unroll
        for (int m = 0; m < 14; m++) {
            float4 xv = xb2[m];
            av += wv[m].x * xv.x + wv[m].y * xv.y + wv[m].z * xv.z + wv[m].w * xv.w;
        }
        g_q[(size_t)n * FDIM + c] = silu_f(aq);
        g_k[(size_t)n * FDIM + c] = silu_f(ak);
        g_v[(size_t)n * FDIM + c] = av;
    }
}

// 512 threads, 16 warps: warp w -> (g = w>>1: rows 16g..16g+15, p = w&1: cols 112p..)
__global__ __launch_bounds__(512, 1) void fused_edge_kernel(
    const float* __restrict__ rbf, const float* __restrict__ cut,
    const int* __restrict__ idx_i, const int* __restrict__ idx_j,
    const float* __restrict__ ev,
    const float* __restrict__ W1r, const float* __restrict__ b1r,
    const float* __restrict__ W1s, const float* __restrict__ b1s,
    const float* __restrict__ b2r, const float* __restrict__ b2s, int P)
{
    extern __shared__ char smc[];
    const unsigned sb = smem_u32(smc);
    const int t = threadIdx.x, w = t >> 5, L = t & 31;
    const int g = w >> 1, p = w & 1;
    const int rw = g * 16;
    const int e0 = blockIdx.x * TE;

    float* cut_s = (float*)(smc + OFF_CUT);
    float* b2c_s = (float*)(smc + OFF_B2C);
    int*   ii_s  = (int*)(smc + OFF_II);
    int*   jj_s  = (int*)(smc + OFF_JJ);
    float* l0_s  = (float*)(smc + OFF_L0);

    // ---- stage misc + B1 (hi/lo) ----
    if (t < 224) b2c_s[t] = b2r[t] + b2s[t];
    if (t < TE) {
        int eg = min(e0 + t, P - 1);
        int a = idx_i[eg], b = idx_j[eg];
        ii_s[t] = a; jj_s[t] = b;
        cut_s[t] = (e0 + t < P) ? cut[e0 + t] : 0.f;
        float s0 = 0.f, s1 = 0.f, s2 = 0.f;
        const float* ea = ev + a * NORD;
        const float* eb = ev + b * NORD;
#pragma unroll
        for (int o = 0; o < NORD; o++) {
            float d = eb[o] - ea[o];
            float dd = d * d;
            if (o < 3) s0 += dd; else if (o < 8) s1 += dd; else s2 += dd;
        }
        l0_s[t] = s0; l0_s[128 + t] = s1; l0_s[256 + t] = s2;
    }
    for (int i = t; i < 224 * 48; i += 512) {
        int n = i / 48, k = i - n * 48;
        float v = 0.f;
        if (n < 112) {
            if (k < 32) v = W1r[k * 112 + n];
            else if (k == 35) v = b1r[n];
        } else {
            int n2 = n - 112;
            if (k >= 32 && k < 35) v = W1s[(k - 32) * 112 + n2];
            else if (k == 35) v = b1s[n2];
        }
        __nv_bfloat16 hv = __float2bfloat16(v);
        ((__nv_bfloat16*)(smc + OFF_B1H))[n * 56 + k] = hv;
        ((__nv_bfloat16*)(smc + OFF_B1L))[n * 56 + k] =
            __float2bfloat16(v - __bfloat162float(hv));
    }
    __syncthreads();
    for (int i = t; i < TE * 48; i += 512) {
        int e = i / 48, k = i - e * 48;
        float v = 0.f;
        if (k < 32)      v = ((e0 + e < P) ? rbf[(size_t)(e0 + e) * 32 + k] : 0.f) * cut_s[e];
        else if (k < 35) v = l0_s[(k - 32) * 128 + e];
        else if (k == 35) v = 1.f;
        __nv_bfloat16 hv = __float2bfloat16(v);
        ((__nv_bfloat16*)(smc + OFF_A1H))[e * 56 + k] = hv;
        ((__nv_bfloat16*)(smc + OFF_A1L))[e * 56 + k] =
            __float2bfloat16(v - __bfloat162float(hv));
    }
    __syncthreads();

    // ---- GEMM1: c1[14][4] = A1 @ B1^T  (N-half p) ----
    unsigned ah1[3][4], al1[3][4];
#pragma unroll
    for (int ks = 0; ks < 3; ks++) {
        unsigned row = rw + (L & 15), col = ks * 16 + (L >> 4) * 8;
        ldm4(ah1[ks], sb + OFF_A1H + (row * 56 + col) * 2);
        ldm4(al1[ks], sb + OFF_A1L + (row * 56 + col) * 2);
    }
    float c1[14][4];
#pragma unroll
    for (int j = 0; j < 14; j++)
#pragma unroll
        for (int q = 0; q < 4; q++) c1[j][q] = 0.f;
#pragma unroll
    for (int j2 = 0; j2 < 7; j2++) {
        unsigned n0 = p * 112 + j2 * 16 + (L >> 4) * 8 + (L & 7);
#pragma unroll
        for (int ks = 0; ks < 3; ks++) {
            unsigned off = n0 * 112 + ks * 32 + ((L >> 3) & 1) * 16;
            unsigned bh[4], bl[4];
            ldm4(bh, sb + OFF_B1H + off);
            ldm4(bl, sb + OFF_B1L + off);
            mmabf(c1[2 * j2], ah1[ks], bh);
            mmabf(c1[2 * j2 + 1], ah1[ks], bh + 2);
            mmabf(c1[2 * j2], al1[ks], bh);
            mmabf(c1[2 * j2 + 1], al1[ks], bh + 2);
            mmabf(c1[2 * j2], ah1[ks], bl);
            mmabf(c1[2 * j2 + 1], ah1[ks], bl + 2);
        }
    }
    __syncthreads();   // all GEMM1 smem reads done; A2 overlay safe

    // ---- silu + split -> A2h/A2l smem (ldmatrix layout, 464 B stride) ----
    {
        const int rA = rw + (L >> 2);
        const int cb = 2 * (L & 3);
        char* a2h = smc + OFF_A2H;
        char* a2l = smc + OFF_A2L;
#pragma unroll
        for (int j = 0; j < 7; j++) {
            const int c0 = p * 112 + j * 16 + cb;
            float v0 = silu_f(c1[2 * j][0]), v1 = silu_f(c1[2 * j][1]);
            float v2 = silu_f(c1[2 * j][2]), v3 = silu_f(c1[2 * j][3]);
            float v4 = silu_f(c1[2 * j + 1][0]), v5 = silu_f(c1[2 * j + 1][1]);
            float v6 = silu_f(c1[2 * j + 1][2]), v7 = silu_f(c1[2 * j + 1][3]);
            unsigned hi, lo;
            split2(v0, v1, hi, lo);
            *(unsigned*)(a2h + rA * 464 + c0 * 2) = hi;
            *(unsigned*)(a2l + rA * 464 + c0 * 2) = lo;
            split2(v2, v3, hi, lo);
            *(unsigned*)(a2h + (rA + 8) * 464 + c0 * 2) = hi;
            *(unsigned*)(a2l + (rA + 8) * 464 + c0 * 2) = lo;
            split2(v4, v5, hi, lo);
            *(unsigned*)(a2h + rA * 464 + (c0 + 8) * 2) = hi;
            *(unsigned*)(a2l + rA * 464 + (c0 + 8) * 2) = lo;
            split2(v6, v7, hi, lo);
            *(unsigned*)(a2h + (rA + 8) * 464 + (c0 + 8) * 2) = hi;
            *(unsigned*)(a2l + (rA + 8) * 464 + (c0 + 8) * 2) = lo;
        }
    }
    __syncthreads();

    // ---- GEMM2: barrier-free; A via ldmatrix per ks, B frags from gmem ----
    float c2[14][4];
#pragma unroll
    for (int j = 0; j < 14; j++)
#pragma unroll
        for (int q = 0; q < 4; q++) c2[j][q] = 0.f;
    const uint4* __restrict__ bf = (const uint4*)g_Bf;
    const unsigned a2h_row = sb + OFF_A2H + (rw + (L & 15)) * 464 + ((L >> 4) * 8) * 2;
    const unsigned a2l_row = sb + OFF_A2L + (rw + (L & 15)) * 464 + ((L >> 4) * 8) * 2;

#pragma unroll
    for (int ks = 0; ks < 14; ks++) {
        unsigned Ah[4], Al[4];
        ldm4(Ah, a2h_row + ks * 32);
        ldm4(Al, a2l_row + ks * 32);
        const int base = ((p * 14 + ks) * 7) * 32 + L;
#pragma unroll
        for (int j2 = 0; j2 < 7; j2++) {
            uint4 bh4 = bf[(base + j2 * 32) * 2];
            uint4 bl4 = bf[(base + j2 * 32) * 2 + 1];
            const unsigned* bh = (const unsigned*)&bh4;
            const unsigned* bl = (const unsigned*)&bl4;
            mmabf(c2[2 * j2], Ah, bh);
            mmabf(c2[2 * j2 + 1], Ah, bh + 2);
            mmabf(c2[2 * j2], Al, bh);
            mmabf(c2[2 * j2 + 1], Al, bh + 2);
            mmabf(c2[2 * j2], Ah, bl);
            mmabf(c2[2 * j2 + 1], Ah, bl + 2);
        }
    }
    __syncthreads();   // all A2 reads done; w overlay safe

    // ---- write w (raw, no bias) to smem f32 ----
    {
        float* ws = (float*)(smc + OFF_WS);
        const int rA = rw + (L >> 2);
        const int cb = 2 * (L & 3);
#pragma unroll
        for (int j2 = 0; j2 < 7; j2++) {
            const int c0 = p * 112 + j2 * 16 + cb;
            ws[rA * 228 + c0]           = c2[2 * j2][0];
            ws[rA * 228 + c0 + 1]       = c2[2 * j2][1];
            ws[(rA + 8) * 228 + c0]     = c2[2 * j2][2];
            ws[(rA + 8) * 228 + c0 + 1] = c2[2 * j2][3];
            ws[rA * 228 + c0 + 8]           = c2[2 * j2 + 1][0];
            ws[rA * 228 + c0 + 9]           = c2[2 * j2 + 1][1];
            ws[(rA + 8) * 228 + c0 + 8]     = c2[2 * j2 + 1][2];
            ws[(rA + 8) * 228 + c0 + 9]     = c2[2 * j2 + 1][3];
        }
    }
    __syncthreads();

    // ---- epilogue: alpha[e][h] = cut * sum_c q_i[c] k_j[c] (w[c]+b2[c]) ----
    {
        const float* ws = (const float*)(smc + OFF_WS);
        const int e = t & 127;
        const int hb = t >> 7;           // 0..3
        const int ni = ii_s[e], nj = jj_s[e];
        const float ce = cut_s[e];
        const float* qp = g_q + (size_t)ni * FDIM;
        const float* kp = g_k + (size_t)nj * FDIM;
#pragma unroll
        for (int it = 0; it < 2; it++) {
            const int h = hb + 4 * it;
            if (h < 7) {
                float s = 0.f;
#pragma unroll
                for (int m = 0; m < 8; m++) {
                    const int c = h * 32 + 4 * m;
                    float4 q4 = *(const float4*)(qp + c);
                    float4 k4 = *(const float4*)(kp + c);
                    s += q4.x * k4.x * (ws[e * 228 + c]     + b2c_s[c]);
                    s += q4.y * k4.y * (ws[e * 228 + c + 1] + b2c_s[c + 1]);
                    s += q4.z * k4.z * (ws[e * 228 + c + 2] + b2c_s[c + 2]);
                    s += q4.w * k4.w * (ws[e * 228 + c + 3] + b2c_s[c + 3]);
                }
                if (e0 + e < P) g_alpha[(size_t)(e0 + e) * 8 + h] = s * ce;
            }
        }
    }
}

// 1024 threads: (c = t&255, quarter q = t>>8). Each handles 32 edges serially.
__global__ __launch_bounds__(1024) void scatter_kernel(
    const float* __restrict__ ylm, const int* __restrict__ idx_i,
    const int* __restrict__ idx_j, float* __restrict__ outx,
    float* __restrict__ outev, int P)
{
    __shared__ float alp_s[7 * TE];
    __shared__ float ylm_s[TE * NORD];
    __shared__ int ii_s[TE], jj_s[TE];
    const int t = threadIdx.x;
    const int e0 = blockIdx.x * TE;
    const int nE = min(TE, P - e0);

    if (t < TE) {
        int eg = min(e0 + t, P - 1);
        ii_s[t] = idx_i[eg];
        jj_s[t] = idx_j[eg];
    }
    for (int i = t; i < 7 * TE; i += 1024) {
        int h = i >> 7, e = i & 127;
        alp_s[i] = (e0 + e < P) ? g_alpha[(size_t)(e0 + e) * 8 + h] : 0.f;
    }
    for (int i = t; i < TE * NORD; i += 1024)
        ylm_s[i] = (e0 + i / NORD < P) ? ylm[(size_t)e0 * NORD + i] : 0.f;
    __syncthreads();

    const int c = t & 255;
    const int q = t >> 8;
    const int eb = q * 32;
    if (eb >= nE) return;
    const int ee = min(eb + 32, nE);

    if (c < FDIM) {
        int hc = c / 56;
        const float* arow = alp_s + hc * TE;
        int icur = ii_s[eb];
        float a2 = 0.f;
        for (int e = eb; e < ee; e++) {
            int ie = ii_s[e];
            if (ie != icur) {
                atomicAdd(outx + (size_t)icur * FDIM + c, a2);
                a2 = 0.f; icur = ie;
            }
            a2 += arow[e] * g_v[(size_t)jj_s[e] * FDIM + c];
        }
        atomicAdd(outx + (size_t)icur * FDIM + c, a2);
    } else if (c < FDIM + NORD) {
        int o = c - FDIM;
        int hd = (o < 3) ? 4 : (o < 8) ? 5 : 6;
        const float* arow = alp_s + hd * TE;
        int icur = ii_s[eb];
        float a2 = 0.f;
        for (int e = eb; e < ee; e++) {
            int ie = ii_s[e];
            if (ie != icur) {
                atomicAdd(outev + (size_t)icur * NORD + o, a2);
                a2 = 0.f; icur = ie;
            }
            a2 += arow[e] * ylm_s[e * NORD + o];
        }
        atomicAdd(outev + (size_t)icur * NORD + o, a2);
    }
}

extern "C" void kernel_launch(void* const* d_in, const int* in_sizes, int n_in,
                              void* d_out, int out_size)
{
    const float* x    = (const float*)d_in[0];
    const float* ev   = (const float*)d_in[1];
    const float* rbf  = (const float*)d_in[2];
    const float* ylm  = (const float*)d_in[3];
    const float* cutp = (const float*)d_in[4];
    const int*   idxi = (const int*)d_in[5];
    const int*   idxj = (const int*)d_in[6];
    const float* W1r  = (const float*)d_in[7];
    const float* b1r  = (const float*)d_in[8];
    const float* W2r  = (const float*)d_in[9];
    const float* b2r  = (const float*)d_in[10];
    const float* W1s  = (const float*)d_in[11];
    const float* b1s  = (const float*)d_in[12];
    const float* W2s  = (const float*)d_in[13];
    const float* b2s  = (const float*)d_in[14];
    const float* Wq   = (const float*)d_in[15];
    const float* Wk   = (const float*)d_in[16];
    const float* Wv   = (const float*)d_in[17];

    int N = in_sizes[0] / FDIM;
    int P = in_sizes[4];
    float* out   = (float*)d_out;
    float* outx  = out;
    float* outev = out + (size_t)N * FDIM;

    zero_kernel<<<(out_size / 4 + 255) / 256, 256>>>(out, out_size);
    prep_bf_kernel<<<(6272 + 255) / 256, 256>>>(W2r, W2s);
    node_kernel<<<1024, 224>>>(x, Wq, Wk, Wv, N);

    cudaFuncSetAttribute(fused_edge_kernel,
                         cudaFuncAttributeMaxDynamicSharedMemorySize, SM_TOTAL);
    int nb = (P + TE - 1) / TE;
    fused_edge_kernel<<<nb, 512, SM_TOTAL>>>(rbf, cutp, idxi, idxj, ev,
                                             W1r, b1r, W1s, b1s, b2r, b2s, P);
    scatter_kernel<<<nb, 1024>>>(ylm, idxi, idxj, outx, outev, P);
}

// round 16
// speedup vs baseline: 1.3828x; 1.3440x over previous
#include <cuda_runtime.h>
#include <cuda_fp16.h>

#define FDIM 224
#define NORD 15
#define NMAX 25008
#define PMAX 400128
#define TE   128

__device__ float g_q[NMAX * FDIM];
__device__ float g_k[NMAX * FDIM];
__device__ float g_v[NMAX * FDIM];
__device__ float g_alpha[(size_t)PMAX * 8];
__device__ unsigned g_Bf[2 * 14 * 7 * 32 * 4];   // B2 fp16 fragments (uint4 each)

// smem byte offsets
#define OFF_CUT   0
#define OFF_B2C   512
#define OFF_II    1408
#define OFF_JJ    1920
#define OFF_L0    2432
// phase 1 (GEMM1 operands), dead after GEMM1:
#define OFF_B1H   4096
#define OFF_A1H   29184
// phase 2 (A2 fp16, ldmatrix layout, 464 B row stride), overlays phase 1:
#define OFF_A2H   4096
// phase 3 (w f32, 228-float row stride), overlays phase 2:
#define OFF_WS    4096
#define SM_TOTAL  122880

__device__ __forceinline__ unsigned smem_u32(const void* p) {
    unsigned a;
    asm("{ .reg .u64 t; cvta.to.shared.u64 t, %1; cvt.u32.u64 %0, t; }" : "=r"(a) : "l"(p));
    return a;
}
__device__ __forceinline__ float silu_f(float x) {
    return __fdividef(x, 1.0f + __expf(-x));
}
__device__ __forceinline__ void ldm4(unsigned* r, unsigned addr) {
    asm volatile("ldmatrix.sync.aligned.m8n8.x4.shared.b16 {%0,%1,%2,%3}, [%4];"
                 : "=r"(r[0]), "=r"(r[1]), "=r"(r[2]), "=r"(r[3]) : "r"(addr) : "memory");
}
__device__ __forceinline__ void mmafp(float* c, const unsigned* a, const unsigned* b) {
    asm volatile("mma.sync.aligned.m16n8k16.row.col.f32.f16.f16.f32 "
                 "{%0,%1,%2,%3}, {%4,%5,%6,%7}, {%8,%9}, {%0,%1,%2,%3};"
                 : "+f"(c[0]), "+f"(c[1]), "+f"(c[2]), "+f"(c[3])
                 : "r"(a[0]), "r"(a[1]), "r"(a[2]), "r"(a[3]), "r"(b[0]), "r"(b[1]));
}
__device__ __forceinline__ unsigned packh(float a, float b) {
    __half2 t = __floats2half2_rn(a, b);
    return *(unsigned*)&t;
}

__global__ void zero_kernel(float* out, int n) {
    int i = blockIdx.x * blockDim.x + threadIdx.x;
    int n4 = n >> 2;
    if (i < n4) ((float4*)out)[i] = make_float4(0.f, 0.f, 0.f, 0.f);
    if (i < (n & 3)) out[n4 * 4 + i] = 0.f;
}

// Pre-pack W2cat into per-lane fp16 MMA B fragments.
// entry id = ((p*14+ks)*7+j2)*32 + L  ->  uint4 (4 packed half2)
__global__ void prep_bf_kernel(const float* __restrict__ W2r, const float* __restrict__ W2s) {
    int id = blockIdx.x * blockDim.x + threadIdx.x;
    if (id >= 6272) return;
    int L = id & 31, rest = id >> 5;
    int j2 = rest % 7, pk = rest / 7;
    int ks = pk % 14, p = pk / 14;
    int n0 = p * 112 + j2 * 16 + (L >> 2);
    int c0 = ks * 16 + (L & 3) * 2;
    unsigned u[4];
#pragma unroll
    for (int i = 0; i < 4; i++) {
        int n = n0 + (i >> 1) * 8;
        int c = c0 + (i & 1) * 8;
        float V0 = (c < 112) ? W2r[c * 224 + n] : W2s[(c - 112) * 224 + n];
        float V1 = (c + 1 < 112) ? W2r[(c + 1) * 224 + n] : W2s[(c + 1 - 112) * 224 + n];
        u[i] = packh(V0, V1);
    }
    ((uint4*)g_Bf)[id] = make_uint4(u[0], u[1], u[2], u[3]);
}

__global__ __launch_bounds__(224) void node_kernel(
    const float* __restrict__ x, const float* __restrict__ Wq,
    const float* __restrict__ Wk, const float* __restrict__ Wv, int N)
{
    __shared__ float xs[FDIM];
    const int c = threadIdx.x;
    const int h = c >> 5, i = c & 31;
    const int h2 = c / 56, i2 = c - h2 * 56;
    float4 wq[8], wk[8], wv[14];
    const float4* q4 = (const float4*)(Wq + (h * 32 + i) * 32);
    const float4* k4 = (const float4*)(Wk + (h * 32 + i) * 32);
    const float4* v4 = (const float4*)(Wv + (h2 * 56 + i2) * 56);
#pragma unroll
    for (int m = 0; m < 8; m++) { wq[m] = q4[m]; wk[m] = k4[m]; }
#pragma unroll
    for (int m = 0; m < 14; m++) wv[m] = v4[m];
    for (int n = blockIdx.x; n < N; n += gridDim.x) {
        __syncthreads();
        xs[c] = x[(size_t)n * FDIM + c];
        __syncthreads();
        float aq = 0.f, ak = 0.f, av = 0.f;
        const float4* xb = (const float4*)(xs + h * 32);
#pragma unroll
        for (int m = 0; m < 8; m++) {
            float4 xv = xb[m];
            aq += wq[m].x * xv.x + wq[m].y * xv.y + wq[m].z * xv.z + wq[m].w * xv.w;
            ak += wk[m].x * xv.x + wk[m].y * xv.y + wk[m].z * xv.z + wk[m].w * xv.w;
        }
        const float4* xb2 = (const float4*)(xs + h2 * 56);
#pragma unroll
        for (int m = 0; m < 14; m++) {
            float4 xv = xb2[m];
            av += wv[m].x * xv.x + wv[m].y * xv.y + wv[m].z * xv.z + wv[m].w * xv.w;
        }
        g_q[(size_t)n * FDIM + c] = silu_f(aq);
        g_k[(size_t)n * FDIM + c] = silu_f(ak);
        g_v[(size_t)n * FDIM + c] = av;
    }
}

// 512 threads, 16 warps: warp w -> (g = w>>1: rows 16g..16g+15, p = w&1: cols 112p..)
__global__ __launch_bounds__(512, 1) void fused_edge_kernel(
    const float* __restrict__ rbf, const float* __restrict__ cut,
    const int* __restrict__ idx_i, const int* __restrict__ idx_j,
    const float* __restrict__ ev,
    const float* __restrict__ W1r, const float* __restrict__ b1r,
    const float* __restrict__ W1s, const float* __restrict__ b1s,
    const float* __restrict__ b2r, const float* __restrict__ b2s, int P)
{
    extern __shared__ char smc[];
    const unsigned sb = smem_u32(smc);
    const int t = threadIdx.x, w = t >> 5, L = t & 31;
    const int g = w >> 1, p = w & 1;
    const int rw = g * 16;
    const int e0 = blockIdx.x * TE;

    float* cut_s = (float*)(smc + OFF_CUT);
    float* b2c_s = (float*)(smc + OFF_B2C);
    int*   ii_s  = (int*)(smc + OFF_II);
    int*   jj_s  = (int*)(smc + OFF_JJ);
    float* l0_s  = (float*)(smc + OFF_L0);

    // ---- stage misc + B1 + A1 (fp16) ----
    if (t < 224) b2c_s[t] = b2r[t] + b2s[t];
    if (t < TE) {
        int eg = min(e0 + t, P - 1);
        int a = idx_i[eg], b = idx_j[eg];
        ii_s[t] = a; jj_s[t] = b;
        cut_s[t] = (e0 + t < P) ? cut[e0 + t] : 0.f;
        float s0 = 0.f, s1 = 0.f, s2 = 0.f;
        const float* ea = ev + a * NORD;
        const float* eb = ev + b * NORD;
#pragma unroll
        for (int o = 0; o < NORD; o++) {
            float d = eb[o] - ea[o];
            float dd = d * d;
            if (o < 3) s0 += dd; else if (o < 8) s1 += dd; else s2 += dd;
        }
        l0_s[t] = s0; l0_s[128 + t] = s1; l0_s[256 + t] = s2;
    }
    for (int i = t; i < 224 * 48; i += 512) {
        int n = i / 48, k = i - n * 48;
        float v = 0.f;
        if (n < 112) {
            if (k < 32) v = W1r[k * 112 + n];
            else if (k == 35) v = b1r[n];
        } else {
            int n2 = n - 112;
            if (k >= 32 && k < 35) v = W1s[(k - 32) * 112 + n2];
            else if (k == 35) v = b1s[n2];
        }
        ((__half*)(smc + OFF_B1H))[n * 56 + k] = __float2half_rn(v);
    }
    __syncthreads();
    for (int i = t; i < TE * 48; i += 512) {
        int e = i / 48, k = i - e * 48;
        float v = 0.f;
        if (k < 32)      v = ((e0 + e < P) ? rbf[(size_t)(e0 + e) * 32 + k] : 0.f) * cut_s[e];
        else if (k < 35) v = l0_s[(k - 32) * 128 + e];
        else if (k == 35) v = 1.f;
        ((__half*)(smc + OFF_A1H))[e * 56 + k] = __float2half_rn(v);
    }
    __syncthreads();

    // ---- GEMM1: c1[14][4] = A1 @ B1^T  (N-half p), fp16 single-term ----
    unsigned ah1[3][4];
#pragma unroll
    for (int ks = 0; ks < 3; ks++) {
        unsigned row = rw + (L & 15), col = ks * 16 + (L >> 4) * 8;
        ldm4(ah1[ks], sb + OFF_A1H + (row * 56 + col) * 2);
    }
    float c1[14][4];
#pragma unroll
    for (int j = 0; j < 14; j++)
#pragma unroll
        for (int q = 0; q < 4; q++) c1[j][q] = 0.f;
#pragma unroll
    for (int j2 = 0; j2 < 7; j2++) {
        unsigned n0 = p * 112 + j2 * 16 + (L >> 4) * 8 + (L & 7);
#pragma unroll
        for (int ks = 0; ks < 3; ks++) {
            unsigned off = n0 * 112 + ks * 32 + ((L >> 3) & 1) * 16;
            unsigned bh[4];
            ldm4(bh, sb + OFF_B1H + off);
            mmafp(c1[2 * j2], ah1[ks], bh);
            mmafp(c1[2 * j2 + 1], ah1[ks], bh + 2);
        }
    }
    __syncthreads();   // all GEMM1 smem reads done; A2 overlay safe

    // ---- silu -> A2 fp16 smem (ldmatrix layout, 464 B stride) ----
    {
        const int rA = rw + (L >> 2);
        const int cb = 2 * (L & 3);
        char* a2h = smc + OFF_A2H;
#pragma unroll
        for (int j = 0; j < 7; j++) {
            const int c0 = p * 112 + j * 16 + cb;
            float v0 = silu_f(c1[2 * j][0]), v1 = silu_f(c1[2 * j][1]);
            float v2 = silu_f(c1[2 * j][2]), v3 = silu_f(c1[2 * j][3]);
            float v4 = silu_f(c1[2 * j + 1][0]), v5 = silu_f(c1[2 * j + 1][1]);
            float v6 = silu_f(c1[2 * j + 1][2]), v7 = silu_f(c1[2 * j + 1][3]);
            *(unsigned*)(a2h + rA * 464 + c0 * 2) = packh(v0, v1);
            *(unsigned*)(a2h + (rA + 8) * 464 + c0 * 2) = packh(v2, v3);
            *(unsigned*)(a2h + rA * 464 + (c0 + 8) * 2) = packh(v4, v5);
            *(unsigned*)(a2h + (rA + 8) * 464 + (c0 + 8) * 2) = packh(v6, v7);
        }
    }
    __syncthreads();

    // ---- GEMM2: barrier-free; A via ldmatrix per ks, B frags from gmem ----
    float c2[14][4];
#pragma unroll
    for (int j = 0; j < 14; j++)
#pragma unroll
        for (int q = 0; q < 4; q++) c2[j][q] = 0.f;
    const uint4* __restrict__ bf = (const uint4*)g_Bf;
    const unsigned a2h_row = sb + OFF_A2H + (rw + (L & 15)) * 464 + ((L >> 4) * 8) * 2;

#pragma unroll
    for (int ks = 0; ks < 14; ks++) {
        unsigned Ah[4];
        ldm4(Ah, a2h_row + ks * 32);
        const int base = ((p * 14 + ks) * 7) * 32 + L;
#pragma unroll
        for (int j2 = 0; j2 < 7; j2++) {
            uint4 bh4 = bf[base + j2 * 32];
            const unsigned* bh = (const unsigned*)&bh4;
            mmafp(c2[2 * j2], Ah, bh);
            mmafp(c2[2 * j2 + 1], Ah, bh + 2);
        }
    }
    __syncthreads();   // all A2 reads done; w overlay safe

    // ---- write w (raw, no bias) to smem f32 ----
    {
        float* ws = (float*)(smc + OFF_WS);
        const int rA = rw + (L >> 2);
        const int cb = 2 * (L & 3);
#pragma unroll
        for (int j2 = 0; j2 < 7; j2++) {
            const int c0 = p * 112 + j2 * 16 + cb;
            ws[rA * 228 + c0]           = c2[2 * j2][0];
            ws[rA * 228 + c0 + 1]       = c2[2 * j2][1];
            ws[(rA + 8) * 228 + c0]     = c2[2 * j2][2];
            ws[(rA + 8) * 228 + c0 + 1] = c2[2 * j2][3];
            ws[rA * 228 + c0 + 8]           = c2[2 * j2 + 1][0];
            ws[rA * 228 + c0 + 9]           = c2[2 * j2 + 1][1];
            ws[(rA + 8) * 228 + c0 + 8]     = c2[2 * j2 + 1][2];
            ws[(rA + 8) * 228 + c0 + 9]     = c2[2 * j2 + 1][3];
        }
    }
    __syncthreads();

    // ---- epilogue: alpha[e][h] = cut * sum_c q_i[c] k_j[c] (w[c]+b2[c]) ----
    {
        const float* ws = (const float*)(smc + OFF_WS);
        const int e = t & 127;
        const int hb = t >> 7;           // 0..3
        const int ni = ii_s[e], nj = jj_s[e];
        const float ce = cut_s[e];
        const float* qp = g_q + (size_t)ni * FDIM;
        const float* kp = g_k + (size_t)nj * FDIM;
#pragma unroll
        for (int it = 0; it < 2; it++) {
            const int h = hb + 4 * it;
            if (h < 7) {
                float s = 0.f;
#pragma unroll
                for (int m = 0; m < 8; m++) {
                    const int c = h * 32 + 4 * m;
                    float4 q4 = *(const float4*)(qp + c);
                    float4 k4 = *(const float4*)(kp + c);
                    s += q4.x * k4.x * (ws[e * 228 + c]     + b2c_s[c]);
                    s += q4.y * k4.y * (ws[e * 228 + c + 1] + b2c_s[c + 1]);
                    s += q4.z * k4.z * (ws[e * 228 + c + 2] + b2c_s[c + 2]);
                    s += q4.w * k4.w * (ws[e * 228 + c + 3] + b2c_s[c + 3]);
                }
                if (e0 + e < P) g_alpha[(size_t)(e0 + e) * 8 + h] = s * ce;
            }
        }
    }
}

// 1024 threads: (c = t&255, quarter q = t>>8). Each handles 32 edges serially.
__global__ __launch_bounds__(1024) void scatter_kernel(
    const float* __restrict__ ylm, const int* __restrict__ idx_i,
    const int* __restrict__ idx_j, float* __restrict__ outx,
    float* __restrict__ outev, int P)
{
    __shared__ float alp_s[7 * TE];
    __shared__ float ylm_s[TE * NORD];
    __shared__ int ii_s[TE], jj_s[TE];
    const int t = threadIdx.x;
    const int e0 = blockIdx.x * TE;
    const int nE = min(TE, P - e0);

    if (t < TE) {
        int eg = min(e0 + t, P - 1);
        ii_s[t] = idx_i[eg];
        jj_s[t] = idx_j[eg];
    }
    for (int i = t; i < 7 * TE; i += 1024) {
        int h = i >> 7, e = i & 127;
        alp_s[i] = (e0 + e < P) ? g_alpha[(size_t)(e0 + e) * 8 + h] : 0.f;
    }
    for (int i = t; i < TE * NORD; i += 1024)
        ylm_s[i] = (e0 + i / NORD < P) ? ylm[(size_t)e0 * NORD + i] : 0.f;
    __syncthreads();

    const int c = t & 255;
    const int q = t >> 8;
    const int eb = q * 32;
    if (eb >= nE) return;
    const int ee = min(eb + 32, nE);

    if (c < FDIM) {
        int hc = c / 56;
        const float* arow = alp_s + hc * TE;
        int icur = ii_s[eb];
        float a2 = 0.f;
        for (int e = eb; e < ee; e++) {
            int ie = ii_s[e];
            if (ie != icur) {
                atomicAdd(outx + (size_t)icur * FDIM + c, a2);
                a2 = 0.f; icur = ie;
            }
            a2 += arow[e] * g_v[(size_t)jj_s[e] * FDIM + c];
        }
        atomicAdd(outx + (size_t)icur * FDIM + c, a2);
    } else if (c < FDIM + NORD) {
        int o = c - FDIM;
        int hd = (o < 3) ? 4 : (o < 8) ? 5 : 6;
        const float* arow = alp_s + hd * TE;
        int icur = ii_s[eb];
        float a2 = 0.f;
        for (int e = eb; e < ee; e++) {
            int ie = ii_s[e];
            if (ie != icur) {
                atomicAdd(outev + (size_t)icur * NORD + o, a2);
                a2 = 0.f; icur = ie;
            }
            a2 += arow[e] * ylm_s[e * NORD + o];
        }
        atomicAdd(outev + (size_t)icur * NORD + o, a2);
    }
}

extern "C" void kernel_launch(void* const* d_in, const int* in_sizes, int n_in,
                              void* d_out, int out_size)
{
    const float* x    = (const float*)d_in[0];
    const float* ev   = (const float*)d_in[1];
    const float* rbf  = (const float*)d_in[2];
    const float* ylm  = (const float*)d_in[3];
    const float* cutp = (const float*)d_in[4];
    const int*   idxi = (const int*)d_in[5];
    const int*   idxj = (const int*)d_in[6];
    const float* W1r  = (const float*)d_in[7];
    const float* b1r  = (const float*)d_in[8];
    const float* W2r  = (const float*)d_in[9];
    const float* b2r  = (const float*)d_in[10];
    const float* W1s  = (const float*)d_in[11];
    const float* b1s  = (const float*)d_in[12];
    const float* W2s  = (const float*)d_in[13];
    const float* b2s  = (const float*)d_in[14];
    const float* Wq   = (const float*)d_in[15];
    const float* Wk   = (const float*)d_in[16];
    const float* Wv   = (const float*)d_in[17];

    int N = in_sizes[0] / FDIM;
    int P = in_sizes[4];
    float* out   = (float*)d_out;
    float* outx  = out;
    float* outev = out + (size_t)N * FDIM;

    zero_kernel<<<(out_size / 4 + 255) / 256, 256>>>(out, out_size);
    prep_bf_kernel<<<(6272 + 255) / 256, 256>>>(W2r, W2s);
    node_kernel<<<1024, 224>>>(x, Wq, Wk, Wv, N);

    cudaFuncSetAttribute(fused_edge_kernel,
                         cudaFuncAttributeMaxDynamicSharedMemorySize, SM_TOTAL);
    int nb = (P + TE - 1) / TE;
    fused_edge_kernel<<<nb, 512, SM_TOTAL>>>(rbf, cutp, idxi, idxj, ev,
                                             W1r, b1r, W1s, b1s, b2r, b2s, P);
    scatter_kernel<<<nb, 1024>>>(ylm, idxi, idxj, outx, outev, P);
}